// round 14
// baseline (speedup 1.0000x reference)
#include <cuda_runtime.h>
#include <cuda_fp16.h>
#include <cstdint>

#define BT 2048
#define NF 128
#define CC 256

// Device globals (no allocations)
__device__ uint32_t g_WqkPh[CC * CC / 2];    // fragment-packed half2 B: n<128 Wq, else Wk
__device__ uint32_t g_WctPh[CC * CC / 2];    // fragment-packed half2 B: Wc = Wg@Wv
__device__ float    g_bc[CC];                // Wg @ bv + bg

__device__ __forceinline__ uint32_t pk(float a, float b) {
    __half2 h = __floats2half2_rn(a, b);
    return *(uint32_t*)&h;
}
__device__ __forceinline__ uint32_t smem_u32(const void* p) {
    uint32_t a;
    asm("{ .reg .u64 t; cvta.to.shared.u64 t, %1; cvt.u32.u64 %0, t; }" : "=r"(a) : "l"(p));
    return a;
}
#define CP16(d, s) asm volatile("cp.async.ca.shared.global [%0], [%1], 16;" :: "r"(d), "l"(s) : "memory")
#define CP_COMMIT() asm volatile("cp.async.commit_group;" ::: "memory")
#define CP_WAIT2()  asm volatile("cp.async.wait_group 2;" ::: "memory")

__device__ __forceinline__ void mma16(float c[4], uint4 a, uint32_t b0, uint32_t b1) {
    asm volatile(
        "mma.sync.aligned.m16n8k16.row.col.f32.f16.f16.f32 "
        "{%0,%1,%2,%3},{%4,%5,%6,%7},{%8,%9},{%0,%1,%2,%3};"
        : "+f"(c[0]), "+f"(c[1]), "+f"(c[2]), "+f"(c[3])
        : "r"(a.x), "r"(a.y), "r"(a.z), "r"(a.w), "r"(b0), "r"(b1));
}

// A-pack word index, 32-row slabs (m16n8k16 row fragment order).
__device__ __forceinline__ int a_w(int S, int m, int k) {
    int slab = m >> 5, mt = (m >> 4) & 1, h = (m >> 3) & 1, g = m & 7;
    int s = k >> 4, kk = k & 15, t = (kk & 7) >> 1, hi = kk >> 3;
    return (((slab * S + s) * 2 + mt) * 32 + g * 4 + t) * 4 + h + 2 * hi;
}
// B-pack word index: word holds halfs (k, k+1) for col n
__device__ __forceinline__ int b_w(int NP, int k, int n) {
    int s = k >> 4, kk = k & 15, t = (kk & 7) >> 1, hi = kk >> 3;
    return ((s * NP + (n >> 3)) * 32 + (n & 7) * 4 + t) * 2 + hi;
}

// One k16 step: warp tile 32 x (NT*8). A mt stride 128 words, B nt stride 64 words.
template <int NT>
__device__ __forceinline__ void step16(float (&acc)[2][8][4], const uint32_t* __restrict__ Aw,
                                       const uint32_t* __restrict__ Bw) {
    uint4 af[2];
#pragma unroll
    for (int mt = 0; mt < 2; mt++) af[mt] = *(const uint4*)(Aw + mt * 128);
#pragma unroll
    for (int nt = 0; nt < NT; nt++) {
        uint2 bf = *(const uint2*)(Bw + nt * 64);
#pragma unroll
        for (int mt = 0; mt < 2; mt++) mma16(acc[mt][nt], af[mt], bf.x, bf.y);
    }
}

// ---------------- merged prep (unchanged from R12) ----------------
__global__ void prep_all(const float* __restrict__ Wq, const float* __restrict__ Wk,
                         const float* __restrict__ Wg, const float* __restrict__ Wv,
                         const float* __restrict__ bv, const float* __restrict__ bg)
{
    __shared__ float sWg[8][256];
    __shared__ float sWct[8][260];
    __shared__ float part[8][8];
    const int bi = blockIdx.x;
    const int j = threadIdx.x;
    const int i0 = bi * 8;
    const int w8 = j >> 5, lane = j & 31;

#pragma unroll
    for (int r = 0; r < 8; r++) sWg[r][j] = Wg[(i0 + r) * 256 + j];
    __syncthreads();

    float acc[8] = {0.f, 0.f, 0.f, 0.f, 0.f, 0.f, 0.f, 0.f};
#pragma unroll 4
    for (int k = 0; k < 256; k++) {
        float wv = Wv[k * 256 + j];
#pragma unroll
        for (int r = 0; r < 8; r++) acc[r] = fmaf(sWg[r][k], wv, acc[r]);
    }
#pragma unroll
    for (int r = 0; r < 8; r++) sWct[r][j] = acc[r];

#pragma unroll
    for (int r = 0; r < 8; r++) {
        float v = sWg[r][j] * bv[j];
#pragma unroll
        for (int off = 16; off; off >>= 1) v += __shfl_xor_sync(0xffffffffu, v, off);
        if (lane == 0) part[r][w8] = v;
    }
    __syncthreads();

    if (j < 8) {
        float s = 0.f;
#pragma unroll
        for (int ww = 0; ww < 8; ww++) s += part[j][ww];
        g_bc[i0 + j] = s + bg[i0 + j];
    }
#pragma unroll
    for (int q = 0; q < 4; q++) {
        int idx = j * 4 + q;
        int nl = idx >> 7, kp = idx & 127;
        g_WctPh[b_w(32, 2 * kp, i0 + nl)] = pk(sWct[nl][2 * kp], sWct[nl][2 * kp + 1]);
    }
#pragma unroll
    for (int q = 0; q < 4; q++) {
        int p2 = bi * 1024 + j * 4 + q;
        int kp = p2 >> 8, n = p2 & 255;
        float q0, q1;
        if (n < 128) { q0 = Wq[n * 256 + 2 * kp]; q1 = Wq[n * 256 + 2 * kp + 1]; }
        else         { q0 = Wk[(n - 128) * 256 + 2 * kp]; q1 = Wk[(n - 128) * 256 + 2 * kp + 1]; }
        g_WqkPh[b_w(32, 2 * kp, n)] = pk(q0, q1);
    }
}

// SMEM word map (per CTA, 100352 B): scr[512] | A1[16384] | BB[8192 = 4 x 2048 ring]
constexpr int OFF_SCR = 0;
constexpr int OFF_A   = 512;
constexpr int OFF_BB  = OFF_A + 16384;
constexpr int SMEM_W  = OFF_BB + 8192;       // 25088 words
constexpr int SMEM_BYTES = SMEM_W * 4;       // 100352 B

__global__ void __launch_bounds__(256, 2)
fused_kernel(const float* __restrict__ x, const float* __restrict__ ee,
             const float* __restrict__ adj, const float* __restrict__ alpha_p,
             const float* __restrict__ bq, const float* __restrict__ bk,
             const float* __restrict__ gamma, const float* __restrict__ beta,
             float* __restrict__ out)
{
    extern __shared__ uint32_t smw[];
    float*    scr = (float*)(smw + OFF_SCR);   // softmax sums (256) then LN mean/rstd (256)
    uint32_t* A1  = smw + OFF_A;
    uint32_t* BB  = smw + OFF_BB;
    const uint32_t bbu = smem_u32(smw + OFF_BB);

    const int tid = threadIdx.x;
    const int w = tid >> 5, lane = tid & 31;
    const int g = lane >> 2, t = lane & 3;
    // N-split ids (phases 1,2,4): 4(M) x 2(N)
    const int wmN = w >> 1, wnN = w & 1;
    const int mrowN = wmN * 32;
    // M-split ids (phase 3): 2(M) x 4(N)
    const int wmM = w >> 2, wnM = w & 3;
    const int b = blockIdx.x;
    const float* xb = x + (size_t)b * (NF * CC);

    float acc[2][8][4];
    uint32_t held[32];

    // Half-N double-chunk stream (2048 words). ci<8 -> first pass half, else second.
    // p1: first pass = K half (gp 16-31, +1024); p4: first pass = cols 0-127 (+0).
#define ISSUE_P(ci, gW, firstoff) do { \
    if ((ci) < 16) { \
        uint32_t d = bbu + (((ci) & 3) * 2048 + tid * 8) * 4; \
        const uint32_t* s_ = (gW) + ((ci) & 7) * 4096 + (tid >> 7) * 2048 \
                           + (((ci) < 8) ? (firstoff) : (1024 - (firstoff))) + ((tid * 8) & 1023); \
        CP16(d, s_); CP16(d + 16, s_ + 4); \
    } \
    CP_COMMIT(); \
} while (0)

#define ZACC() do { \
    _Pragma("unroll") for (int mt = 0; mt < 2; mt++) \
    _Pragma("unroll") for (int nt = 0; nt < 8; nt++) \
    _Pragma("unroll") for (int e = 0; e < 4; e++) acc[mt][nt][e] = 0.f; \
} while (0)

    ISSUE_P(0, g_WqkPh, 1024);
    ISSUE_P(1, g_WqkPh, 1024);

    // ===== stage xe = fp16(x + ee) in A-pack (S=16) =====
#pragma unroll 4
    for (int j = 0; j < 32; j++) {
        int f = j * 256 + tid;
        int r = f >> 6, c0 = (f & 63) << 2;
        float4 v = __ldg((const float4*)(xb + r * 256 + c0));
        float4 e = __ldg((const float4*)(ee + r * 256 + c0));
        int w0 = a_w(16, r, c0);
        A1[w0]     = pk(v.x + e.x, v.y + e.y);
        A1[w0 + 4] = pk(v.z + e.z, v.w + e.w);
    }

    // ===== Phase 1: [K | Q] passes =====
    ZACC();
    for (int ci = 0; ci < 8; ci++) {      // K pass (cols 128-255)
        ISSUE_P(ci + 2, g_WqkPh, 1024);
        CP_WAIT2();
        __syncthreads();
#pragma unroll
        for (int sl = 0; sl < 2; sl++)
            step16<8>(acc, A1 + wmN * 4096 + ((ci & 7) * 2 + sl) * 256 + lane * 4,
                      BB + (ci & 3) * 2048 + sl * 1024 + wnN * 512 + lane * 2);
    }
    // K results -> held (fp16, +bk)
#pragma unroll
    for (int nt = 0; nt < 8; nt++) {
        const int ck = wnN * 64 + nt * 8 + 2 * t;
        float2 bb = __ldg((const float2*)&bk[ck]);
#pragma unroll
        for (int mt = 0; mt < 2; mt++) {
            held[(mt * 8 + nt) * 2 + 0] = pk(acc[mt][nt][0] + bb.x, acc[mt][nt][1] + bb.y);
            held[(mt * 8 + nt) * 2 + 1] = pk(acc[mt][nt][2] + bb.x, acc[mt][nt][3] + bb.y);
        }
    }
    ZACC();
    for (int ci = 8; ci < 16; ci++) {     // Q pass (cols 0-127)
        ISSUE_P(ci + 2, g_WqkPh, 1024);
        CP_WAIT2();
        __syncthreads();
#pragma unroll
        for (int sl = 0; sl < 2; sl++)
            step16<8>(acc, A1 + wmN * 4096 + ((ci & 7) * 2 + sl) * 256 + lane * 4,
                      BB + (ci & 3) * 2048 + sl * 1024 + wnN * 512 + lane * 2);
    }
    __syncthreads();   // all xe reads done; A1 reusable

    // Q -> A1 lower (a_w S=8), K(held) -> A1 upper (b_w NP=16)
#pragma unroll
    for (int nt = 0; nt < 8; nt++) {
        const int n = wnN * 64 + nt * 8 + 2 * t;
        float2 bb = __ldg((const float2*)&bq[n]);
#pragma unroll
        for (int mt = 0; mt < 2; mt++) {
            const int r0 = mrowN + mt * 16 + g, r1 = r0 + 8;
            A1[a_w(8, r0, n)] = pk(acc[mt][nt][0] + bb.x, acc[mt][nt][1] + bb.y);
            A1[a_w(8, r1, n)] = pk(acc[mt][nt][2] + bb.x, acc[mt][nt][3] + bb.y);
            A1[8192 + b_w(16, n, r0)] = held[(mt * 8 + nt) * 2 + 0];
            A1[8192 + b_w(16, n, r1)] = held[(mt * 8 + nt) * 2 + 1];
        }
    }
    __syncthreads();

    // ===== Phase 2: scores = Q @ K^T =====
    ZACC();
#pragma unroll
    for (int s = 0; s < 8; s++)
        step16<8>(acc, A1 + wmN * 2048 + s * 256 + lane * 4,
                  A1 + 8192 + s * 1024 + wnN * 512 + lane * 2);

    // ===== softmax (no max pass) -> attn overwrites Q (A1 lower) =====
    {
        const float fa = __ldg(alpha_p);
        const float invs = 0.08838834764831845f;
#pragma unroll
        for (int mt = 0; mt < 2; mt++)
#pragma unroll
            for (int h = 0; h < 2; h++) {
                const int r = mrowN + mt * 16 + g + h * 8;
                float s = 0.f;
#pragma unroll
                for (int nt = 0; nt < 8; nt++) {
                    const int col = wnN * 64 + nt * 8 + 2 * t;
                    float2 av = __ldg((const float2*)&adj[r * 128 + col]);
                    float p0 = __expf(acc[mt][nt][h * 2 + 0] * invs + fa * fmaxf(av.x, 0.f));
                    float p1 = __expf(acc[mt][nt][h * 2 + 1] * invs + fa * fmaxf(av.y, 0.f));
                    acc[mt][nt][h * 2 + 0] = p0;
                    acc[mt][nt][h * 2 + 1] = p1;
                    s += p0 + p1;
                }
                s += __shfl_xor_sync(0xffffffffu, s, 1);
                s += __shfl_xor_sync(0xffffffffu, s, 2);
                scr[r * 2 + wnN] = s;
            }
        __syncthreads();
#pragma unroll
        for (int mt = 0; mt < 2; mt++)
#pragma unroll
            for (int h = 0; h < 2; h++) {
                const int r = mrowN + mt * 16 + g + h * 8;
                const float inv = 1.f / (scr[r * 2] + scr[r * 2 + 1]);
#pragma unroll
                for (int nt = 0; nt < 8; nt++) {
                    const int col = wnN * 64 + nt * 8 + 2 * t;
                    A1[a_w(8, r, col)] = pk(acc[mt][nt][h * 2 + 0] * inv,
                                            acc[mt][nt][h * 2 + 1] * inv);
                }
            }
    }
    __syncthreads();

    // ===== Phase 3: ax = attn @ x  (M-split passes; x tiles full-N in BB 2x4096) =====
    const int rp = tid >> 4, c8 = (tid & 15) << 4;
    const int stt = rp & 3, shi = (rp >> 2) & 1, ssl = rp >> 3;
#define STAGE_X(si_) do { \
    const float* xs_ = xb + ((si_) & 3) * 32 * 256 + 2 * rp * 256 + c8; \
    uint32_t* dst_ = BB + ((si_) & 1) * 4096 + ssl * 2048; \
    float av_[16], bv_[16]; \
    _Pragma("unroll") for (int q = 0; q < 4; q++) { \
        float4 va = __ldg((const float4*)(xs_ + q * 4)); \
        float4 vb = __ldg((const float4*)(xs_ + 256 + q * 4)); \
        av_[q*4+0]=va.x; av_[q*4+1]=va.y; av_[q*4+2]=va.z; av_[q*4+3]=va.w; \
        bv_[q*4+0]=vb.x; bv_[q*4+1]=vb.y; bv_[q*4+2]=vb.z; bv_[q*4+3]=vb.w; \
    } \
    _Pragma("unroll") for (int i = 0; i < 16; i++) { \
        int n_ = c8 + i; \
        dst_[((n_ >> 3) * 32 + (n_ & 7) * 4 + stt) * 2 + shi] = pk(av_[i], bv_[i]); \
    } \
} while (0)

    ZACC();
    STAGE_X(0);
    __syncthreads();
    for (int si = 0; si < 8; si++) {
        if (si < 7) STAGE_X(si + 1);
        const int pass = si >> 2, c = si & 3;
#pragma unroll
        for (int sl = 0; sl < 2; sl++)
            step16<8>(acc, A1 + (pass * 2 + wmM) * 2048 + (c * 2 + sl) * 256 + lane * 4,
                      BB + (si & 1) * 4096 + sl * 2048 + wnM * 512 + lane * 2);
        if (si == 3) {   // pass-0 ax epilogue -> A1 upper (Kt dead); no reader yet
#pragma unroll
            for (int nt = 0; nt < 8; nt++) {
                const int n = wnM * 64 + nt * 8 + 2 * t;
#pragma unroll
                for (int mt = 0; mt < 2; mt++) {
                    const int r0 = wmM * 32 + mt * 16 + g, r1 = r0 + 8;
                    A1[8192 + wmM * 4096 + (a_w(16, r0, n) - wmM * 4096)] = pk(acc[mt][nt][0], acc[mt][nt][1]);
                    A1[8192 + wmM * 4096 + (a_w(16, r1, n) - wmM * 4096)] = pk(acc[mt][nt][2], acc[mt][nt][3]);
                }
            }
            ZACC();
        }
        __syncthreads();
    }
    // pass-1 ax epilogue -> A1 lower (attn dead; barrier above guarantees)
    ISSUE_P(0, g_WctPh, 0);
    ISSUE_P(1, g_WctPh, 0);
#pragma unroll
    for (int nt = 0; nt < 8; nt++) {
        const int n = wnM * 64 + nt * 8 + 2 * t;
#pragma unroll
        for (int mt = 0; mt < 2; mt++) {
            const int r0 = 64 + wmM * 32 + mt * 16 + g, r1 = r0 + 8;
            A1[wmM * 4096 + (a_w(16, r0, n) - (2 + wmM) * 4096)] = pk(acc[mt][nt][0], acc[mt][nt][1]);
            A1[wmM * 4096 + (a_w(16, r1, n) - (2 + wmM) * 4096)] = pk(acc[mt][nt][2], acc[mt][nt][3]);
        }
    }
    __syncthreads();

    // ===== Phase 4: z = ax @ Wc^T  (N-split passes; ax slab remap) =====
    const uint32_t* axA = A1 + ((wmN < 2) ? (8192 + wmN * 4096) : ((wmN - 2) * 4096));
    ZACC();
    for (int ci = 0; ci < 8; ci++) {      // cols 0-127
        ISSUE_P(ci + 2, g_WctPh, 0);
        CP_WAIT2();
        __syncthreads();
#pragma unroll
        for (int sl = 0; sl < 2; sl++)
            step16<8>(acc, axA + ((ci & 7) * 2 + sl) * 256 + lane * 4,
                      BB + (ci & 3) * 2048 + sl * 1024 + wnN * 512 + lane * 2);
    }
    // h0 (cols 0-127) -> held fp16
#pragma unroll
    for (int nt = 0; nt < 8; nt++) {
        const int n = wnN * 64 + nt * 8 + 2 * t;
        float2 bc2 = __ldg((const float2*)&g_bc[n]);
#pragma unroll
        for (int mt = 0; mt < 2; mt++) {
            const int r0 = mrowN + mt * 16 + g, r1 = r0 + 8;
            float2 xv0 = __ldg((const float2*)&xb[r0 * 256 + n]);
            float2 xv1 = __ldg((const float2*)&xb[r1 * 256 + n]);
            held[(mt * 8 + nt) * 2 + 0] = pk(fmaxf(acc[mt][nt][0] + bc2.x, 0.f) + xv0.x,
                                             fmaxf(acc[mt][nt][1] + bc2.y, 0.f) + xv0.y);
            held[(mt * 8 + nt) * 2 + 1] = pk(fmaxf(acc[mt][nt][2] + bc2.x, 0.f) + xv1.x,
                                             fmaxf(acc[mt][nt][3] + bc2.y, 0.f) + xv1.y);
        }
    }
    ZACC();
    for (int ci = 8; ci < 16; ci++) {     // cols 128-255
        ISSUE_P(ci + 2, g_WctPh, 0);
        CP_WAIT2();
        __syncthreads();
#pragma unroll
        for (int sl = 0; sl < 2; sl++)
            step16<8>(acc, axA + ((ci & 7) * 2 + sl) * 256 + lane * 4,
                      BB + (ci & 3) * 2048 + sl * 1024 + wnN * 512 + lane * 2);
    }
    __syncthreads();   // all ax reads done; A1 reusable for h

    // h layout (bank-swizzled): cols<128 -> A1+8192, cols>=128 -> A1+0; word = r*64 + (c2 ^ (r&63))
#pragma unroll
    for (int nt = 0; nt < 8; nt++) {
        const int n1 = 128 + wnN * 64 + nt * 8 + 2 * t;
        float2 bc2 = __ldg((const float2*)&g_bc[n1]);
        const int n0 = wnN * 64 + nt * 8 + 2 * t;
#pragma unroll
        for (int mt = 0; mt < 2; mt++) {
            const int r0 = mrowN + mt * 16 + g, r1 = r0 + 8;
            float2 xv0 = __ldg((const float2*)&xb[r0 * 256 + n1]);
            float2 xv1 = __ldg((const float2*)&xb[r1 * 256 + n1]);
            A1[r0 * 64 + ((((n1 - 128) >> 1)) ^ (r0 & 63))] =
                pk(fmaxf(acc[mt][nt][0] + bc2.x, 0.f) + xv0.x,
                   fmaxf(acc[mt][nt][1] + bc2.y, 0.f) + xv0.y);
            A1[r1 * 64 + ((((n1 - 128) >> 1)) ^ (r1 & 63))] =
                pk(fmaxf(acc[mt][nt][2] + bc2.x, 0.f) + xv1.x,
                   fmaxf(acc[mt][nt][3] + bc2.y, 0.f) + xv1.y);
            A1[8192 + r0 * 64 + (((n0 >> 1)) ^ (r0 & 63))] = held[(mt * 8 + nt) * 2 + 0];
            A1[8192 + r1 * 64 + (((n0 >> 1)) ^ (r1 & 63))] = held[(mt * 8 + nt) * 2 + 1];
        }
    }
    __syncthreads();

    // ===== LayerNorm: reduce then coalesced write =====
    {
        const int r = tid >> 1, half = tid & 1;
        const uint32_t* hb = A1 + (half ? 0 : 8192) + r * 64;
        float s1 = 0.f, s2 = 0.f;
#pragma unroll 8
        for (int i = 0; i < 64; i++) {
            __half2 h2 = *(const __half2*)&hb[i ^ (r & 63)];
            float2 f = __half22float2(h2);
            s1 += f.x + f.y;
            s2 += f.x * f.x + f.y * f.y;
        }
        s1 += __shfl_xor_sync(0xffffffffu, s1, 1);
        s2 += __shfl_xor_sync(0xffffffffu, s2, 1);
        if (half == 0) {
            float mean = s1 * (1.f / 256.f);
            scr[r] = mean;
            scr[128 + r] = rsqrtf(s2 * (1.f / 256.f) - mean * mean + 1e-5f);
        }
    }
    __syncthreads();
    float* ob = out + (size_t)b * (NF * CC);
#pragma unroll 4
    for (int j = 0; j < 64; j++) {
        int f = j * 256 + tid;
        int r = f >> 7, n2 = f & 127;
        int n = n2 * 2;
        const uint32_t hw = A1[(n < 128 ? 8192 : 0) + r * 64 + (((n & 127) >> 1) ^ (r & 63))];
        float2 h2 = __half22float2(*(const __half2*)&hw);
        const float mean = scr[r], rstd = scr[128 + r];
        float2 g2 = __ldg((const float2*)&gamma[n]);
        float2 b2 = __ldg((const float2*)&beta[n]);
        float2 o;
        o.x = (h2.x - mean) * rstd * g2.x + b2.x;
        o.y = (h2.y - mean) * rstd * g2.y + b2.y;
        *(float2*)(ob + r * 256 + n) = o;
    }
#undef ISSUE_P
#undef ZACC
#undef STAGE_X
}

extern "C" void kernel_launch(void* const* d_in, const int* in_sizes, int n_in,
                              void* d_out, int out_size)
{
    (void)in_sizes; (void)n_in; (void)out_size;
    const float* x     = (const float*)d_in[0];
    const float* ee    = (const float*)d_in[1];
    const float* adj   = (const float*)d_in[2];
    const float* alpha = (const float*)d_in[3];
    const float* Wq    = (const float*)d_in[4];
    const float* bq    = (const float*)d_in[5];
    const float* Wk    = (const float*)d_in[6];
    const float* bk    = (const float*)d_in[7];
    const float* Wv    = (const float*)d_in[8];
    const float* bv    = (const float*)d_in[9];
    const float* Wg    = (const float*)d_in[10];
    const float* bg    = (const float*)d_in[11];
    const float* gamma = (const float*)d_in[12];
    const float* beta  = (const float*)d_in[13];
    float* out = (float*)d_out;

    cudaFuncSetAttribute(fused_kernel, cudaFuncAttributeMaxDynamicSharedMemorySize, SMEM_BYTES);
    prep_all<<<32, 256>>>(Wq, Wk, Wg, Wv, bv, bg);
    fused_kernel<<<BT, 256, SMEM_BYTES>>>(x, ee, adj, alpha, bq, bk, gamma, beta, out);
}

// round 15
// speedup vs baseline: 1.3888x; 1.3888x over previous
#include <cuda_runtime.h>
#include <cuda_fp16.h>
#include <cstdint>

#define BT 2048
#define NF 128
#define CC 256

// Device globals (no allocations)
__device__ uint32_t g_WqkPh[CC * CC / 2];    // fragment-packed half2 B: n<128 Wq, else Wk
__device__ uint32_t g_WctPh[CC * CC / 2];    // fragment-packed half2 B: Wc = Wg@Wv
__device__ float    g_bc[CC];                // Wg @ bv + bg

__device__ __forceinline__ uint32_t pk(float a, float b) {
    __half2 h = __floats2half2_rn(a, b);
    return *(uint32_t*)&h;
}
__device__ __forceinline__ uint32_t smem_u32(const void* p) {
    uint32_t a;
    asm("{ .reg .u64 t; cvta.to.shared.u64 t, %1; cvt.u32.u64 %0, t; }" : "=r"(a) : "l"(p));
    return a;
}
#define CP16(d, s) asm volatile("cp.async.ca.shared.global [%0], [%1], 16;" :: "r"(d), "l"(s) : "memory")
#define CP_COMMIT() asm volatile("cp.async.commit_group;" ::: "memory")
#define CP_WAIT2()  asm volatile("cp.async.wait_group 2;" ::: "memory")

__device__ __forceinline__ void mma16(float c[4], uint4 a, uint32_t b0, uint32_t b1) {
    asm volatile(
        "mma.sync.aligned.m16n8k16.row.col.f32.f16.f16.f32 "
        "{%0,%1,%2,%3},{%4,%5,%6,%7},{%8,%9},{%0,%1,%2,%3};"
        : "+f"(c[0]), "+f"(c[1]), "+f"(c[2]), "+f"(c[3])
        : "r"(a.x), "r"(a.y), "r"(a.z), "r"(a.w), "r"(b0), "r"(b1));
}

// B-pack word index (used by prep only): word holds halfs (k, k+1) for col n
__device__ __forceinline__ int b_w(int NP, int k, int n) {
    int s = k >> 4, kk = k & 15, t = (kk & 7) >> 1, hi = kk >> 3;
    return ((s * NP + (n >> 3)) * 32 + (n & 7) * 4 + t) * 2 + hi;
}

// One k16 step: warp tile 32 x (NT*8). A mt stride 128 words, B nt stride 64 words.
template <int NT>
__device__ __forceinline__ void step16(float (&acc)[2][8][4], const uint32_t* __restrict__ Aw,
                                       const uint32_t* __restrict__ Bw) {
    uint4 af[2];
#pragma unroll
    for (int mt = 0; mt < 2; mt++) af[mt] = *(const uint4*)(Aw + mt * 128);
#pragma unroll
    for (int nt = 0; nt < NT; nt++) {
        uint2 bf = *(const uint2*)(Bw + nt * 64);
#pragma unroll
        for (int mt = 0; mt < 2; mt++) mma16(acc[mt][nt], af[mt], bf.x, bf.y);
    }
}

// ---------------- merged prep: 64 blocks x 4 Wct rows ----------------
__global__ void prep_all(const float* __restrict__ Wq, const float* __restrict__ Wk,
                         const float* __restrict__ Wg, const float* __restrict__ Wv,
                         const float* __restrict__ bv, const float* __restrict__ bg)
{
    __shared__ float sWg[4][256];
    __shared__ float sWct[4][260];
    __shared__ float part[4][8];
    const int bi = blockIdx.x;      // 0..63, owns Wct rows i0..i0+3
    const int j = threadIdx.x;      // 0..255
    const int i0 = bi * 4;
    const int w8 = j >> 5, lane = j & 31;

#pragma unroll
    for (int r = 0; r < 4; r++) sWg[r][j] = Wg[(i0 + r) * 256 + j];
    __syncthreads();

    float acc[4] = {0.f, 0.f, 0.f, 0.f};
#pragma unroll 4
    for (int k = 0; k < 256; k++) {
        float wv = Wv[k * 256 + j];
#pragma unroll
        for (int r = 0; r < 4; r++) acc[r] = fmaf(sWg[r][k], wv, acc[r]);
    }
#pragma unroll
    for (int r = 0; r < 4; r++) sWct[r][j] = acc[r];

#pragma unroll
    for (int r = 0; r < 4; r++) {
        float v = sWg[r][j] * bv[j];
#pragma unroll
        for (int off = 16; off; off >>= 1) v += __shfl_xor_sync(0xffffffffu, v, off);
        if (lane == 0) part[r][w8] = v;
    }
    __syncthreads();

    if (j < 4) {
        float s = 0.f;
#pragma unroll
        for (int ww = 0; ww < 8; ww++) s += part[j][ww];
        g_bc[i0 + j] = s + bg[i0 + j];
    }
    // pack this block's 4 Wct rows (512 words, 2 per thread)
#pragma unroll
    for (int q = 0; q < 2; q++) {
        int idx = j * 2 + q;
        int nl = idx >> 7, kp = idx & 127;
        g_WctPh[b_w(32, 2 * kp, i0 + nl)] = pk(sWct[nl][2 * kp], sWct[nl][2 * kp + 1]);
    }
    // pack this block's 1/64 slice of Wqk
#pragma unroll
    for (int q = 0; q < 2; q++) {
        int p2 = bi * 512 + j * 2 + q;
        int kp = p2 >> 8, n = p2 & 255;
        float q0, q1;
        if (n < 128) { q0 = Wq[n * 256 + 2 * kp]; q1 = Wq[n * 256 + 2 * kp + 1]; }
        else         { q0 = Wk[(n - 128) * 256 + 2 * kp]; q1 = Wk[(n - 128) * 256 + 2 * kp + 1]; }
        g_WqkPh[b_w(32, 2 * kp, n)] = pk(q0, q1);
    }
}

// SMEM word map: scr[1024] | A1[16384] (xe -> Q|Kt -> attn|Kt -> ax) | BB[16384]
constexpr int OFF_SCR = 0;
constexpr int OFF_A   = 1024;
constexpr int OFF_BB  = OFF_A + 16384;
constexpr int SMEM_W  = OFF_BB + 16384;      // 33792 words
constexpr int SMEM_BYTES = SMEM_W * 4;       // 135168 B

__global__ void __launch_bounds__(512, 1)
fused_kernel(const float* __restrict__ x, const float* __restrict__ ee,
             const float* __restrict__ adj, const float* __restrict__ alpha_p,
             const float* __restrict__ bq, const float* __restrict__ bk,
             const float* __restrict__ gamma, const float* __restrict__ beta,
             float* __restrict__ out)
{
    extern __shared__ uint32_t smw[];
    float*    scr = (float*)(smw + OFF_SCR);   // softmax sums / LN partials
    uint32_t* A1  = smw + OFF_A;               // xe(S16) / Q(S8)+Kt / attn+Kt / ax(S16)
    uint32_t* BB  = smw + OFF_BB;
    const uint32_t bbu = smem_u32(smw + OFF_BB);

    const int tid = threadIdx.x;
    const int w = tid >> 5, lane = tid & 31;
    const int g = lane >> 2, t = lane & 3;
    const int wm = w >> 2, wn = w & 3;          // 4 x 4 warp grid
    const int mrow = wm * 32;
    const int ncol = wn * 64;                   // phases 1,3,4 (N=256)
    const int ncol2 = wn * 32;                  // phase 2 (N=128)
    const int b = blockIdx.x;
    const float* xb = x + (size_t)b * (NF * CC);

    float acc[2][8][4];

    // weight double-chunk cc = 4096 words; thread copies 8 words (linear, prepacked)
#define ISSUE_W2(cc, gW) do { \
    if ((cc) < 8) { \
        uint32_t d = bbu + (((cc) & 3) * 4096 + tid * 8) * 4; \
        const uint32_t* s_ = (gW) + (cc) * 4096 + tid * 8; \
        CP16(d, s_); CP16(d + 16, s_ + 4); \
    } \
    CP_COMMIT(); \
} while (0)

#define ZACC() do { \
    _Pragma("unroll") for (int mt = 0; mt < 2; mt++) \
    _Pragma("unroll") for (int nt = 0; nt < 8; nt++) \
    _Pragma("unroll") for (int e = 0; e < 4; e++) acc[mt][nt][e] = 0.f; \
} while (0)

    ISSUE_W2(0, g_WqkPh);
    ISSUE_W2(1, g_WqkPh);

    // ===== stage xe = fp16(x+ee), fragment-owner mapping: conflict-free uint4 STS =====
#pragma unroll
    for (int it = 0; it < 8; it++) {
        int u = it * 16 + w;                   // unit = (slab, s, mt)
        int slab = u >> 5, s = (u >> 1) & 15, mt = u & 1;
        int r0 = slab * 32 + mt * 16 + g;
        int k0 = s * 16 + 2 * t;
        const float* px = xb + r0 * 256 + k0;
        const float* pe = ee + r0 * 256 + k0;
        float2 a0 = __ldg((const float2*)px);
        float2 a1 = __ldg((const float2*)(px + 8 * 256));
        float2 a2 = __ldg((const float2*)(px + 8));
        float2 a3 = __ldg((const float2*)(px + 8 * 256 + 8));
        float2 e0 = __ldg((const float2*)pe);
        float2 e1 = __ldg((const float2*)(pe + 8 * 256));
        float2 e2 = __ldg((const float2*)(pe + 8));
        float2 e3 = __ldg((const float2*)(pe + 8 * 256 + 8));
        uint4 v;
        v.x = pk(a0.x + e0.x, a0.y + e0.y);
        v.y = pk(a1.x + e1.x, a1.y + e1.y);
        v.z = pk(a2.x + e2.x, a2.y + e2.y);
        v.w = pk(a3.x + e3.x, a3.y + e3.y);
        ((uint4*)A1)[((slab * 16 + s) * 2 + mt) * 32 + lane] = v;
    }

    // ===== Phase 1: [Q|K] = xe @ Wqk^T  (8 double-ksteps) =====
    ZACC();
    for (int cc = 0; cc < 8; cc++) {
        ISSUE_W2(cc + 2, g_WqkPh);
        CP_WAIT2();
        __syncthreads();
#pragma unroll
        for (int sl = 0; sl < 2; sl++)
            step16<8>(acc, A1 + wm * 4096 + (2 * cc + sl) * 256 + lane * 4,
                      BB + (cc & 3) * 4096 + sl * 2048 + wn * 512 + lane * 2);
    }
    __syncthreads();   // all xe reads done before Q/Kt overwrite A1

    // epilogue: Q-pack (wn<2) uint4 / Kt-pack (wn>=2) uint2 — conflict-free
    if (wn < 2) {
#pragma unroll
        for (int np = 0; np < 4; np++) {
            int n0 = ncol + np * 16 + 2 * t;
            float2 b0 = __ldg((const float2*)&bq[n0]);
            float2 b1 = __ldg((const float2*)&bq[n0 + 8]);
#pragma unroll
            for (int mt = 0; mt < 2; mt++) {
                uint4 v;
                v.x = pk(acc[mt][2 * np][0] + b0.x, acc[mt][2 * np][1] + b0.y);
                v.y = pk(acc[mt][2 * np][2] + b0.x, acc[mt][2 * np][3] + b0.y);
                v.z = pk(acc[mt][2 * np + 1][0] + b1.x, acc[mt][2 * np + 1][1] + b1.y);
                v.w = pk(acc[mt][2 * np + 1][2] + b1.x, acc[mt][2 * np + 1][3] + b1.y);
                ((uint4*)A1)[((wm * 8 + wn * 4 + np) * 2 + mt) * 32 + lane] = v;
            }
        }
    } else {
#pragma unroll
        for (int np = 0; np < 4; np++) {
            int ck0 = (wn - 2) * 64 + np * 16 + 2 * t;
            float2 b0 = __ldg((const float2*)&bk[ck0]);
            float2 b1 = __ldg((const float2*)&bk[ck0 + 8]);
            int sb = (wn - 2) * 4 + np;
#pragma unroll
            for (int mt = 0; mt < 2; mt++) {
                int gp0 = wm * 4 + mt * 2;
                uint2 v0, v1;
                v0.x = pk(acc[mt][2 * np][0] + b0.x, acc[mt][2 * np][1] + b0.y);
                v0.y = pk(acc[mt][2 * np + 1][0] + b1.x, acc[mt][2 * np + 1][1] + b1.y);
                v1.x = pk(acc[mt][2 * np][2] + b0.x, acc[mt][2 * np][3] + b0.y);
                v1.y = pk(acc[mt][2 * np + 1][2] + b1.x, acc[mt][2 * np + 1][3] + b1.y);
                ((uint2*)(A1 + 8192))[(sb * 16 + gp0) * 32 + lane] = v0;
                ((uint2*)(A1 + 8192))[(sb * 16 + gp0 + 1) * 32 + lane] = v1;
            }
        }
    }
    __syncthreads();

    // ===== Phase 2: scores = Q @ K^T  (8 ksteps, warp tile 32x32) =====
    ZACC();
#pragma unroll
    for (int s = 0; s < 8; s++)
        step16<4>(acc, A1 + wm * 2048 + s * 256 + lane * 4,
                  A1 + 8192 + s * 1024 + wn * 256 + lane * 2);

    // ===== softmax (no max pass) -> attn-pack, conflict-free uint4 =====
    {
        const float fa = __ldg(alpha_p);
        const float invs = 0.08838834764831845f;
#pragma unroll
        for (int mt = 0; mt < 2; mt++)
#pragma unroll
            for (int h = 0; h < 2; h++) {
                const int r = mrow + mt * 16 + g + h * 8;
                float s = 0.f;
#pragma unroll
                for (int nt = 0; nt < 4; nt++) {
                    const int col = ncol2 + nt * 8 + 2 * t;
                    float2 av = __ldg((const float2*)&adj[r * 128 + col]);
                    float p0 = __expf(acc[mt][nt][h * 2 + 0] * invs + fa * fmaxf(av.x, 0.f));
                    float p1 = __expf(acc[mt][nt][h * 2 + 1] * invs + fa * fmaxf(av.y, 0.f));
                    acc[mt][nt][h * 2 + 0] = p0;
                    acc[mt][nt][h * 2 + 1] = p1;
                    s += p0 + p1;
                }
                s += __shfl_xor_sync(0xffffffffu, s, 1);
                s += __shfl_xor_sync(0xffffffffu, s, 2);
                scr[r * 4 + wn] = s;
            }
        __syncthreads();
#pragma unroll
        for (int mt = 0; mt < 2; mt++) {
            const int r0 = mrow + mt * 16 + g;
            const float* s0 = &scr[r0 * 4];
            const float* s1 = &scr[(r0 + 8) * 4];
            const float inv0 = 1.f / (s0[0] + s0[1] + s0[2] + s0[3]);
            const float inv1 = 1.f / (s1[0] + s1[1] + s1[2] + s1[3]);
#pragma unroll
            for (int np = 0; np < 2; np++) {
                uint4 v;
                v.x = pk(acc[mt][2 * np][0] * inv0, acc[mt][2 * np][1] * inv0);
                v.y = pk(acc[mt][2 * np][2] * inv1, acc[mt][2 * np][3] * inv1);
                v.z = pk(acc[mt][2 * np + 1][0] * inv0, acc[mt][2 * np + 1][1] * inv0);
                v.w = pk(acc[mt][2 * np + 1][2] * inv1, acc[mt][2 * np + 1][3] * inv1);
                ((uint4*)A1)[((wm * 8 + wn * 2 + np) * 2 + mt) * 32 + lane] = v;
            }
        }
    }
    __syncthreads();   // attn visible before phase-3 reads

    // ===== Phase 3: ax = attn @ x  (4 chunks, fragment-owner staging, conflict-free) =====
#define STAGE_X3(cidx, buf) do { \
    const float* xs_ = xb + (cidx) * 32 * 256; \
    _Pragma("unroll") \
    for (int it = 0; it < 4; it++) { \
        int u = it * 16 + w; \
        int sl = u >> 5, gp = u & 31; \
        int n_ = gp * 8 + (lane >> 2); \
        const float* p0 = xs_ + (sl * 16 + 2 * (lane & 3)) * 256 + n_; \
        float v0 = __ldg(p0), v1 = __ldg(p0 + 256); \
        float v8 = __ldg(p0 + 8 * 256), v9 = __ldg(p0 + 9 * 256); \
        uint2 vv; vv.x = pk(v0, v1); vv.y = pk(v8, v9); \
        ((uint2*)(buf))[(sl * 32 + gp) * 32 + lane] = vv; \
    } \
} while (0)

    ZACC();
    STAGE_X3(0, BB);
    __syncthreads();
    for (int c = 0; c < 4; c++) {
        if (c < 3) STAGE_X3(c + 1, BB + ((c + 1) & 1) * 4096);
        uint32_t* cur = BB + (c & 1) * 4096;
#pragma unroll
        for (int sl = 0; sl < 2; sl++)
            step16<8>(acc, A1 + wm * 2048 + (c * 2 + sl) * 256 + lane * 4,
                      cur + sl * 2048 + wn * 512 + lane * 2);
        __syncthreads();
    }

    // prefetch first two weight double-chunks of phase 4
    ISSUE_W2(0, g_WctPh);
    ISSUE_W2(1, g_WctPh);

    // epilogue: ax-pack (S=16) uint4, conflict-free (attn/Kt dead)
#pragma unroll
    for (int np = 0; np < 4; np++)
#pragma unroll
        for (int mt = 0; mt < 2; mt++) {
            uint4 v;
            v.x = pk(acc[mt][2 * np][0], acc[mt][2 * np][1]);
            v.y = pk(acc[mt][2 * np][2], acc[mt][2 * np][3]);
            v.z = pk(acc[mt][2 * np + 1][0], acc[mt][2 * np + 1][1]);
            v.w = pk(acc[mt][2 * np + 1][2], acc[mt][2 * np + 1][3]);
            ((uint4*)A1)[((wm * 16 + wn * 4 + np) * 2 + mt) * 32 + lane] = v;
        }
    __syncthreads();

    // ===== Phase 4: z = ax @ Wc^T  (8 double-ksteps) =====
    ZACC();
    for (int cc = 0; cc < 8; cc++) {
        ISSUE_W2(cc + 2, g_WctPh);
        CP_WAIT2();
        __syncthreads();
#pragma unroll
        for (int sl = 0; sl < 2; sl++)
            step16<8>(acc, A1 + wm * 4096 + (2 * cc + sl) * 256 + lane * 4,
                      BB + (cc & 3) * 4096 + sl * 2048 + wn * 512 + lane * 2);
    }

    // ===== LN epilogue: h = relu(z + bc) + x; LayerNorm over C; store =====
#pragma unroll
    for (int mt = 0; mt < 2; mt++)
#pragma unroll
        for (int h = 0; h < 2; h++) {
            const int r = mrow + mt * 16 + g + h * 8;
            float s1 = 0.f, s2 = 0.f;
#pragma unroll
            for (int nt = 0; nt < 8; nt++) {
                const int n = ncol + nt * 8 + 2 * t;
                float2 bc2 = __ldg((const float2*)&g_bc[n]);
                float2 xv = __ldg((const float2*)&xb[r * 256 + n]);
                float h0 = fmaxf(acc[mt][nt][h * 2 + 0] + bc2.x, 0.f) + xv.x;
                float h1 = fmaxf(acc[mt][nt][h * 2 + 1] + bc2.y, 0.f) + xv.y;
                acc[mt][nt][h * 2 + 0] = h0;
                acc[mt][nt][h * 2 + 1] = h1;
                s1 += h0 + h1;
                s2 += h0 * h0 + h1 * h1;
            }
            s1 += __shfl_xor_sync(0xffffffffu, s1, 1);
            s1 += __shfl_xor_sync(0xffffffffu, s1, 2);
            s2 += __shfl_xor_sync(0xffffffffu, s2, 1);
            s2 += __shfl_xor_sync(0xffffffffu, s2, 2);
            scr[r * 4 + wn] = s1;
            scr[512 + r * 4 + wn] = s2;
        }
    __syncthreads();
    float* ob = out + (size_t)b * (NF * CC);
#pragma unroll
    for (int mt = 0; mt < 2; mt++)
#pragma unroll
        for (int h = 0; h < 2; h++) {
            const int r = mrow + mt * 16 + g + h * 8;
            const float S  = scr[r * 4] + scr[r * 4 + 1] + scr[r * 4 + 2] + scr[r * 4 + 3];
            const float Q2 = scr[512 + r * 4] + scr[512 + r * 4 + 1]
                           + scr[512 + r * 4 + 2] + scr[512 + r * 4 + 3];
            const float mean = S * (1.f / 256.f);
            const float rstd = rsqrtf(Q2 * (1.f / 256.f) - mean * mean + 1e-5f);
#pragma unroll
            for (int nt = 0; nt < 8; nt++) {
                const int n = ncol + nt * 8 + 2 * t;
                float2 g2 = __ldg((const float2*)&gamma[n]);
                float2 b2 = __ldg((const float2*)&beta[n]);
                float2 o;
                o.x = (acc[mt][nt][h * 2 + 0] - mean) * rstd * g2.x + b2.x;
                o.y = (acc[mt][nt][h * 2 + 1] - mean) * rstd * g2.y + b2.y;
                *(float2*)(ob + r * 256 + n) = o;
            }
        }
#undef ISSUE_W2
#undef ZACC
#undef STAGE_X3
}

extern "C" void kernel_launch(void* const* d_in, const int* in_sizes, int n_in,
                              void* d_out, int out_size)
{
    (void)in_sizes; (void)n_in; (void)out_size;
    const float* x     = (const float*)d_in[0];
    const float* ee    = (const float*)d_in[1];
    const float* adj   = (const float*)d_in[2];
    const float* alpha = (const float*)d_in[3];
    const float* Wq    = (const float*)d_in[4];
    const float* bq    = (const float*)d_in[5];
    const float* Wk    = (const float*)d_in[6];
    const float* bk    = (const float*)d_in[7];
    const float* Wv    = (const float*)d_in[8];
    const float* bv    = (const float*)d_in[9];
    const float* Wg    = (const float*)d_in[10];
    const float* bg    = (const float*)d_in[11];
    const float* gamma = (const float*)d_in[12];
    const float* beta  = (const float*)d_in[13];
    float* out = (float*)d_out;

    cudaFuncSetAttribute(fused_kernel, cudaFuncAttributeMaxDynamicSharedMemorySize, SMEM_BYTES);
    prep_all<<<64, 256>>>(Wq, Wk, Wg, Wv, bv, bg);
    fused_kernel<<<BT, 512, SMEM_BYTES>>>(x, ee, adj, alpha, bq, bk, gamma, beta, out);
}